// round 17
// baseline (speedup 1.0000x reference)
#include <cuda_runtime.h>
#include <math.h>

// Problem constants
#define Bn   8
#define Nn   2048
#define Cin  64
#define Cout 64
#define Kn   20
#define KSn  20
#define NP   (Bn*Nn)      // 16384 points
#define XK   1504         // packed GEMM inner dim: 1280 agg + 160 g + 64 feat
#define XKH  752          // split-K half (47 tiles of 16)
#define XSTRIDE 1536      // padded row stride (float4 aligned)

// ---------------- scratch (__device__ globals, no allocation) ----------------
__device__ float g_Ft[NP*Cin];            // feature transposed [p][c]   (4 MB)
__device__ int   g_idx[NP*Kn];            // knn indices                 (1.3 MB)
__device__ float g_X[(size_t)NP*XSTRIDE]; // packed per-point vectors    (100 MB)
__device__ float g_Wt[XSTRIDE*Cout];      // packed weights [k][o]
__device__ float g_bias[Cout];
__device__ float g_o1a[Cout*NP];          // pre-BN output half A [o][p] (4 MB)
__device__ float g_o1b[Cout*NP];          // pre-BN output half B [o][p] (4 MB)
__device__ float g_scale[Cout];
__device__ float g_shift[Cout];

// packed f32x2 FMA: d = a*b + d  (two fp32 lanes per instruction)
#define FMA2(d, a, b) \
    asm("fma.rn.f32x2 %0, %1, %2, %0;" : "+l"(d) : "l"(a), "l"(b))

// ---------------- fused prep: transpose (blocks 0..1023) + weights (1024..) ----
// agg block is m-major: X position q (q<1280) holds agg[c][m], c=q&63, m=q>>6
__global__ void k_prep(const float* __restrict__ f,
                       const float* __restrict__ conv_w,
                       const float* __restrict__ mlp_w,
                       const float* __restrict__ mlp_b,
                       const float* __restrict__ mlp_out_w,
                       const float* __restrict__ conv_b,
                       const float* __restrict__ mlp_out_b){
    int bid = blockIdx.x;
    int t = threadIdx.x;
    if (bid < 1024){
        __shared__ float tile[32][33];
        int b = bid >> 7, c0 = ((bid >> 6) & 1)*32, n0 = (bid & 63)*32;
        int tx = t & 31, ty = t >> 5;
        #pragma unroll
        for (int i=0;i<4;i++)
            tile[ty+8*i][tx] = f[b*Cin*Nn + (c0+ty+8*i)*Nn + n0+tx];
        __syncthreads();
        #pragma unroll
        for (int i=0;i<4;i++)
            g_Ft[(b*Nn + n0+ty+8*i)*Cin + c0+tx] = tile[tx][ty+8*i];
    } else {
        int id = (bid - 1024)*256 + t;   // < 1536*64
        int k = id >> 6, o = id & 63;
        float v = 0.f;
        if (k < 1280){
            int c = k & 63, m = k >> 6;
            v = conv_w[o*2560 + c*KSn + m];
        } else if (k < 1440){
            int e = k - 1280;
            int m = e >> 3, j = e & 7;
            const float* cw = conv_w + o*2560 + 1280 + m;   // (64+c2)*20+m
            float s = 0.f;
            if (j < 7){
                for (int c2=0;c2<64;c2++) s += mlp_w[c2*7+j]*cw[c2*20];
            } else {
                for (int c2=0;c2<64;c2++) s += mlp_b[c2]*cw[c2*20];
            }
            v = s;
        } else if (k < XK){
            v = mlp_out_w[o*64 + (k-1440)];
        }
        g_Wt[k*64 + o] = v;
        if (id < 64) g_bias[id] = conv_b[id] + mlp_out_b[id];
    }
}

// ---------------- KNN: dual-query interleaved extraction ---------------------
// Points bank-swizzled; per-lane top-2 register cache per query; extracted
// candidates tracked in per-lane 64-bit slot masks; rescans recompute
// distances (conflict-free banks) excluding extracted slots — exact top-20.
// Two independent queries run lock-step through the extraction loop so each
// warp-collective's latency is covered by the sibling query's issue.
__global__ void __launch_bounds__(128) k_knn(const float* __restrict__ x){
    __shared__ float spx[Nn];
    __shared__ float spy[Nn];
    __shared__ float spz[Nn];
    int t = threadIdx.x, w = t>>5, lane = t&31;
    int b = blockIdx.y;
    const float* xb = x + b*3*Nn;
    for (int e=t; e<Nn; e+=128){
        int se = e ^ ((e>>5)&31);
        spx[se] = xb[e]; spy[se] = xb[Nn+e]; spz[se] = xb[2*Nn+e];
    }
    __syncthreads();
    const unsigned INFU = 0x7F800000u;
    const float INFV = __uint_as_float(INFU);

    for (int i=0;i<2;i++){
        int qA = blockIdx.x*16 + w*4 + i*2;
        int qB = qA + 1;
        int sqA = qA ^ ((qA>>5)&31), sqB = qB ^ ((qB>>5)&31);
        float qxA = spx[sqA], qyA = spy[sqA], qzA = spz[sqA];
        float qxB = spx[sqB], qyB = spy[sqB], qzB = spz[sqB];
        float m1A = INFV, m2A = INFV; int a1A = 0, a2A = 0;
        float m1B = INFV, m2B = INFV; int a1B = 0, a2B = 0;
        unsigned long long maskA = 0ULL, maskB = 0ULL;
        #pragma unroll 8
        for (int tt=0; tt<64; tt++){
            int j  = lane + (tt<<5);
            int sj = j ^ (tt & 31);
            float px = spx[sj], py = spy[sj], pz = spz[sj];
            float dxA = px-qxA, dyA = py-qyA, dzA = pz-qzA;
            float dA = dxA*dxA + dyA*dyA + dzA*dzA;
            float dxB = px-qxB, dyB = py-qyB, dzB = pz-qzB;
            float dB = dxB*dxB + dyB*dyB + dzB*dzB;
            if (dA < m1A){ m2A=m1A; a2A=a1A; m1A=dA; a1A=j; }
            else if (dA < m2A){ m2A=dA; a2A=j; }
            if (dB < m1B){ m2B=m1B; a2B=a1B; m1B=dB; a1B=j; }
            else if (dB < m2B){ m2B=dB; a2B=j; }
        }
        int mynA = 0, mynB = 0;
        for (int kk=0; kk<Kn; kk++){
            unsigned gmA = __reduce_min_sync(0xffffffffu, __float_as_uint(m1A));
            unsigned gmB = __reduce_min_sync(0xffffffffu, __float_as_uint(m1B));
            unsigned bmA = __ballot_sync(0xffffffffu, __float_as_uint(m1A)==gmA);
            unsigned bmB = __ballot_sync(0xffffffffu, __float_as_uint(m1B)==gmB);
            int LA = __ffs(bmA) - 1;
            int LB = __ffs(bmB) - 1;
            int jA = __shfl_sync(0xffffffffu, a1A, LA);
            int jB = __shfl_sync(0xffffffffu, a1B, LB);
            if (lane == kk){ mynA = jA; mynB = jB; }
            if (lane == LA){
                maskA |= 1ULL << (jA >> 5);
                m1A = m2A; a1A = a2A; m2A = INFV;
            }
            if (lane == LB){
                maskB |= 1ULL << (jB >> 5);
                m1B = m2B; a1B = a2B; m2B = INFV;
            }
            unsigned rsA = __ballot_sync(0xffffffffu,
                           (lane==LA) && (__float_as_uint(m1A)==INFU));
            unsigned rsB = __ballot_sync(0xffffffffu,
                           (lane==LB) && (__float_as_uint(m1B)==INFU));
            if (rsA){
                unsigned long long msk = __shfl_sync(0xffffffffu, maskA, LA);
                int tt1 = lane, tt2 = lane + 32;
                int j1 = LA + (tt1<<5), j2 = LA + (tt2<<5);
                float v1 = INFV, v2 = INFV;
                if (!((msk >> tt1) & 1ULL)){
                    int s1i = j1 ^ (tt1 & 31);
                    float dx = spx[s1i]-qxA, dy = spy[s1i]-qyA, dz = spz[s1i]-qzA;
                    v1 = dx*dx + dy*dy + dz*dz;
                }
                if (!((msk >> tt2) & 1ULL)){
                    int s2i = j2 ^ (tt2 & 31);
                    float dx = spx[s2i]-qxA, dy = spy[s2i]-qyA, dz = spz[s2i]-qzA;
                    v2 = dx*dx + dy*dy + dz*dz;
                }
                float nv; int na;
                if (v1 <= v2){ nv = v1; na = j1; } else { nv = v2; na = j2; }
                unsigned r2 = __reduce_min_sync(0xffffffffu, __float_as_uint(nv));
                unsigned b2 = __ballot_sync(0xffffffffu, __float_as_uint(nv)==r2);
                int s2 = __ffs(b2) - 1;
                int na2 = __shfl_sync(0xffffffffu, na, s2);
                if (lane == LA){ m1A = __uint_as_float(r2); a1A = na2; }
            }
            if (rsB){
                unsigned long long msk = __shfl_sync(0xffffffffu, maskB, LB);
                int tt1 = lane, tt2 = lane + 32;
                int j1 = LB + (tt1<<5), j2 = LB + (tt2<<5);
                float v1 = INFV, v2 = INFV;
                if (!((msk >> tt1) & 1ULL)){
                    int s1i = j1 ^ (tt1 & 31);
                    float dx = spx[s1i]-qxB, dy = spy[s1i]-qyB, dz = spz[s1i]-qzB;
                    v1 = dx*dx + dy*dy + dz*dz;
                }
                if (!((msk >> tt2) & 1ULL)){
                    int s2i = j2 ^ (tt2 & 31);
                    float dx = spx[s2i]-qxB, dy = spy[s2i]-qyB, dz = spz[s2i]-qzB;
                    v2 = dx*dx + dy*dy + dz*dz;
                }
                float nv; int na;
                if (v1 <= v2){ nv = v1; na = j1; } else { nv = v2; na = j2; }
                unsigned r2 = __reduce_min_sync(0xffffffffu, __float_as_uint(nv));
                unsigned b2 = __ballot_sync(0xffffffffu, __float_as_uint(nv)==r2);
                int s2 = __ffs(b2) - 1;
                int na2 = __shfl_sync(0xffffffffu, na, s2);
                if (lane == LB){ m1B = __uint_as_float(r2); a1B = na2; }
            }
        }
        if (lane < Kn){
            g_idx[(b*Nn + qA)*Kn + lane] = mynA;
            g_idx[(b*Nn + qB)*Kn + lane] = mynB;
        }
    }
}

// ---------------- per-point: perm + agg + g fused into dnorm ----------------
__global__ void k_point(const float* __restrict__ x,
                        const float* __restrict__ kern,
                        const float* __restrict__ onepad){
    __shared__ int   sidx[2][Kn];
    __shared__ float sSelf[2][3];
    __shared__ __align__(16) float4 sR4[2][Kn];     // (rx,ry,rz,dist)
    __shared__ __align__(16) float sP[2][Kn][24];

    int t = threadIdx.x;
    int half = t >> 6, u = t & 63;
    int p = blockIdx.x*2 + half;
    int b = p >> 11, n = p & 2047;
    float* xrow = g_X + (size_t)p*XSTRIDE;

    if (u < Kn) sidx[half][u] = g_idx[p*Kn + u];
    if (u < 3)  sSelf[half][u] = x[b*3*Nn + u*Nn + n];
    __syncthreads();

    if (u < Kn){
        int j = sidx[half][u];
        float rx = x[b*3*Nn +        j] - sSelf[half][0];
        float ry = x[b*3*Nn +   Nn + j] - sSelf[half][1];
        float rz = x[b*3*Nn + 2*Nn + j] - sSelf[half][2];
        float d  = sqrtf(rx*rx + ry*ry + rz*rz + 1e-12f);
        sR4[half][u] = make_float4(rx, ry, rz, d);
    }
    // self feature row directly to g_X
    xrow[1440 + u] = g_Ft[p*Cin + u];
    __syncthreads();

    // raw perm = relu(rel @ kernals + one_padding)
    #pragma unroll
    for (int e=u; e<Kn*KSn; e+=64){
        int k = e/KSn, m = e - k*KSn;
        float4 r = sR4[half][k];
        float s = r.x*kern[m] + r.y*kern[KSn+m]
                + r.z*kern[2*KSn+m] + onepad[e];
        sP[half][k][m] = fmaxf(s, 0.f);
    }
    __syncthreads();

    // double normalization over k + threshold (column m=u), fused g-vector
    if (u < KSn){
        float s1 = 0.f;
        #pragma unroll
        for (int k=0;k<Kn;k++) s1 += sP[half][k][u];
        float inv1 = 1.f/(s1 + 1e-6f);
        float v[Kn]; float s2 = 0.f;
        #pragma unroll
        for (int k=0;k<Kn;k++){ float q = sP[half][k][u]*inv1; q = q*q; v[k] = q; s2 += q; }
        float inv2 = 1.f/(s2 + 1e-6f);
        float s3 = 0.f;
        float g3 = 0.f, g4 = 0.f, g5 = 0.f, g6 = 0.f;
        #pragma unroll
        for (int k=0;k<Kn;k++){
            float q = v[k]*inv2;
            q = (q > 0.1f) ? q : 0.f;
            sP[half][k][u] = q; s3 += q;
            float4 r = sR4[half][k];
            g3 += r.x*q; g4 += r.y*q; g5 += r.z*q; g6 += r.w*q;
        }
        float sx = sSelf[half][0]*s3;
        float sy = sSelf[half][1]*s3;
        float sz = sSelf[half][2]*s3;
        float4* gx = (float4*)(xrow + 1280 + u*8);
        gx[0] = make_float4(sx, sy, sz, g3);
        gx[1] = make_float4(g4, g5, g6, s3);
    }
    __syncthreads();

    // agg[c][m] = sum_k NF[k][c]*P[k][m]; thread u = channel c, all 20 m.
    {
        const int base = b*Nn;
        float acc[20];
        #pragma unroll
        for (int i=0;i<20;i++) acc[i] = 0.f;
        #pragma unroll
        for (int k=0;k<Kn;k++){
            float vv = g_Ft[(size_t)(base + sidx[half][k])*Cin + u];
            const float4* pr = (const float4*)sP[half][k];
            float4 q0 = pr[0], q1 = pr[1], q2 = pr[2], q3 = pr[3], q4 = pr[4];
            acc[0]+=vv*q0.x;  acc[1]+=vv*q0.y;  acc[2]+=vv*q0.z;  acc[3]+=vv*q0.w;
            acc[4]+=vv*q1.x;  acc[5]+=vv*q1.y;  acc[6]+=vv*q1.z;  acc[7]+=vv*q1.w;
            acc[8]+=vv*q2.x;  acc[9]+=vv*q2.y;  acc[10]+=vv*q2.z; acc[11]+=vv*q2.w;
            acc[12]+=vv*q3.x; acc[13]+=vv*q3.y; acc[14]+=vv*q3.z; acc[15]+=vv*q3.w;
            acc[16]+=vv*q4.x; acc[17]+=vv*q4.y; acc[18]+=vv*q4.z; acc[19]+=vv*q4.w;
        }
        #pragma unroll
        for (int m=0;m<20;m++)
            xrow[m*64 + u] = acc[m];
    }
}

// ---------------- GEMM (split-K=2, FFMA2, double-buffered smem) ----------------
// thread tile: 8 consecutive p-rows (4 packed pairs) x 4 o-columns
__global__ void __launch_bounds__(256) k_gemm(){
    __shared__ float As[2][16][132];
    __shared__ __align__(16) float Bs[2][16][64];
    int t = threadIdx.x;
    int p0 = blockIdx.x * 128;
    int h  = blockIdx.y;
    int k0 = h * XKH;
    int tx = t & 15, ty = t >> 4;
    int arow = t >> 2, aseg = t & 3;       // As loader mapping (rows 0..63 / +64)
    int bk   = t >> 4, bseg = t & 15;      // Bs loader mapping
    unsigned long long acc[4][4];
    #pragma unroll
    for (int i=0;i<4;i++)
        #pragma unroll
        for (int j=0;j<4;j++) acc[i][j] = 0ULL;

    const float* a0p = g_X + (size_t)(p0+arow)*XSTRIDE + aseg*4;
    const float* a1p = g_X + (size_t)(p0+64+arow)*XSTRIDE + aseg*4;
    const float* bp  = g_Wt + bk*64 + bseg*4;

    // preload tile 0 into buffer 0
    {
        float4 v0 = *(const float4*)(a0p + k0);
        float4 v1 = *(const float4*)(a1p + k0);
        float4 wv = *(const float4*)(bp + k0*64);
        As[0][aseg*4+0][arow] = v0.x; As[0][aseg*4+1][arow] = v0.y;
        As[0][aseg*4+2][arow] = v0.z; As[0][aseg*4+3][arow] = v0.w;
        As[0][aseg*4+0][64+arow] = v1.x; As[0][aseg*4+1][64+arow] = v1.y;
        As[0][aseg*4+2][64+arow] = v1.z; As[0][aseg*4+3][64+arow] = v1.w;
        *(float4*)&Bs[0][bk][bseg*4] = wv;
    }
    __syncthreads();

    #pragma unroll 1
    for (int it=0; it<47; it++){
        int cur = it & 1, nxt = cur ^ 1;
        int ktn = k0 + (it+1)*16;
        float4 v0, v1, wv;
        bool more = (it < 46);
        if (more){
            v0 = *(const float4*)(a0p + ktn);
            v1 = *(const float4*)(a1p + ktn);
            wv = *(const float4*)(bp + ktn*64);
        }
        #pragma unroll
        for (int k=0;k<16;k++){
            const float* ar = &As[cur][k][ty*8];
            unsigned long long a0 = *(const unsigned long long*)(ar+0);
            unsigned long long a1 = *(const unsigned long long*)(ar+2);
            unsigned long long a2 = *(const unsigned long long*)(ar+4);
            unsigned long long a3 = *(const unsigned long long*)(ar+6);
            float4 bv = *(const float4*)&Bs[cur][k][tx*4];
            unsigned long long b0,b1,b2,b3;
            asm("mov.b64 %0, {%1, %1};" : "=l"(b0) : "r"(__float_as_uint(bv.x)));
            asm("mov.b64 %0, {%1, %1};" : "=l"(b1) : "r"(__float_as_uint(bv.y)));
            asm("mov.b64 %0, {%1, %1};" : "=l"(b2) : "r"(__float_as_uint(bv.z)));
            asm("mov.b64 %0, {%1, %1};" : "=l"(b3) : "r"(__float_as_uint(bv.w)));
            FMA2(acc[0][0], a0, b0); FMA2(acc[0][1], a0, b1);
            FMA2(acc[0][2], a0, b2); FMA2(acc[0][3], a0, b3);
            FMA2(acc[1][0], a1, b0); FMA2(acc[1][1], a1, b1);
            FMA2(acc[1][2], a1, b2); FMA2(acc[1][3], a1, b3);
            FMA2(acc[2][0], a2, b0); FMA2(acc[2][1], a2, b1);
            FMA2(acc[2][2], a2, b2); FMA2(acc[2][3], a2, b3);
            FMA2(acc[3][0], a3, b0); FMA2(acc[3][1], a3, b1);
            FMA2(acc[3][2], a3, b2); FMA2(acc[3][3], a3, b3);
        }
        if (more){
            As[nxt][aseg*4+0][arow] = v0.x; As[nxt][aseg*4+1][arow] = v0.y;
            As[nxt][aseg*4+2][arow] = v0.z; As[nxt][aseg*4+3][arow] = v0.w;
            As[nxt][aseg*4+0][64+arow] = v1.x; As[nxt][aseg*4+1][64+arow] = v1.y;
            As[nxt][aseg*4+2][64+arow] = v1.z; As[nxt][aseg*4+3][64+arow] = v1.w;
            *(float4*)&Bs[nxt][bk][bseg*4] = wv;
            __syncthreads();
        }
    }
    float* dst = h ? g_o1b : g_o1a;
    #pragma unroll
    for (int j=0;j<4;j++){
        int o = tx*4 + j;
        float bb = h ? 0.f : g_bias[o];
        #pragma unroll
        for (int i=0;i<4;i++){
            float lo = __uint_as_float((unsigned)(acc[i][j] & 0xffffffffULL));
            float hi = __uint_as_float((unsigned)(acc[i][j] >> 32));
            *(float2*)&dst[o*NP + p0 + ty*8 + i*2] = make_float2(lo+bb, hi+bb);
        }
    }
}

// ---------------- BN statistics per channel (float4 reads) ----------------
__global__ void k_bnstat(const float* __restrict__ gamma,
                         const float* __restrict__ beta){
    int o = blockIdx.x, t = threadIdx.x;
    const float4* ra = (const float4*)(g_o1a + o*NP);
    const float4* rb = (const float4*)(g_o1b + o*NP);
    double s = 0.0, s2 = 0.0;
    for (int i=t; i<NP/4; i+=256){
        float4 va = ra[i], vb = rb[i];
        double v0 = (double)(va.x+vb.x), v1 = (double)(va.y+vb.y);
        double v2 = (double)(va.z+vb.z), v3 = (double)(va.w+vb.w);
        s += v0+v1+v2+v3;
        s2 += v0*v0 + v1*v1 + v2*v2 + v3*v3;
    }
    __shared__ double sh1[256], sh2[256];
    sh1[t] = s; sh2[t] = s2;
    __syncthreads();
    for (int off=128; off; off>>=1){
        if (t < off){ sh1[t] += sh1[t+off]; sh2[t] += sh2[t+off]; }
        __syncthreads();
    }
    if (t == 0){
        double mean = sh1[0] / (double)NP;
        double var  = sh2[0] / (double)NP - mean*mean;
        float sc = gamma[o] / sqrtf((float)var + 1e-5f);
        g_scale[o] = sc;
        g_shift[o] = beta[o] - (float)mean * sc;
    }
}

// ---------------- finalize: affine BN + layout [B,C,N] (float4) ----------------
__global__ void k_final(float* __restrict__ out){
    int e4 = blockIdx.x*blockDim.x + threadIdx.x;   // < 262144
    int base = e4 * 4;
    int n = base & 2047;
    int o = (base >> 11) & 63;
    int b = base >> 17;
    int idx = o*NP + b*Nn + n;
    float4 va = *(const float4*)(g_o1a + idx);
    float4 vb = *(const float4*)(g_o1b + idx);
    float sc = g_scale[o], sh = g_shift[o];
    float4 r;
    r.x = (va.x+vb.x)*sc + sh;
    r.y = (va.y+vb.y)*sc + sh;
    r.z = (va.z+vb.z)*sc + sh;
    r.w = (va.w+vb.w)*sc + sh;
    *(float4*)(out + base) = r;
}

// ---------------- launch ----------------
extern "C" void kernel_launch(void* const* d_in, const int* in_sizes, int n_in,
                              void* d_out, int out_size){
    (void)in_sizes; (void)n_in; (void)out_size;
    const float* x         = (const float*)d_in[0];
    const float* feature   = (const float*)d_in[1];
    const float* kernals   = (const float*)d_in[2];
    const float* one_pad   = (const float*)d_in[3];
    const float* mlp_w     = (const float*)d_in[4];
    const float* mlp_b     = (const float*)d_in[5];
    const float* conv_w    = (const float*)d_in[6];
    const float* conv_b    = (const float*)d_in[7];
    const float* mlp_out_w = (const float*)d_in[8];
    const float* mlp_out_b = (const float*)d_in[9];
    const float* bn_gamma  = (const float*)d_in[10];
    const float* bn_beta   = (const float*)d_in[11];
    float* out = (float*)d_out;

    k_prep<<<1024 + 384, 256>>>(feature, conv_w, mlp_w, mlp_b,
                                mlp_out_w, conv_b, mlp_out_b);
    k_knn<<<dim3(Nn/16, Bn), 128>>>(x);
    k_point<<<NP/2, 128>>>(x, kernals, one_pad);
    k_gemm<<<dim3(NP/128, 2), 256>>>();
    k_bnstat<<<Cout, 256>>>(bn_gamma, bn_beta);
    k_final<<<(Bn*Cout*Nn)/1024, 256>>>(out);
}